// round 7
// baseline (speedup 1.0000x reference)
#include <cuda_runtime.h>
#include <cuda_bf16.h>

#define B_    16
#define A_    262144
#define G_    128
#define NTHR  256
#define NBLK  (A_ / NTHR)      /* 1024 */
#define NWARP (NTHR / 32)      /* 8 */

// Per-(batch, block) partials: {sum, count}. Written fresh every launch ->
// no zeroing, fully deterministic (no float atomics anywhere).
__device__ float2   g_part[B_ * NBLK];
__device__ unsigned g_done = 0;   // reset by the last block each launch

__global__ void __launch_bounds__(NTHR)
retina_loss_fused(const float4* __restrict__ bbox,     // [B, A, 4]
                  const float4* __restrict__ anchors,  // [A, 4]
                  const float4* __restrict__ gt,       // [B, G, 4]
                  const int*    __restrict__ midx,     // [B, A]
                  float*        __restrict__ out)
{
    // gt staged in smem, PRE-TRANSFORMED to {gcx, gcy, log(gw), log(gh)}.
    // Turns the hot-loop random gather from ~25 L1tex wavefronts per warp
    // into a ~8-cycle smem gather, and removes 30 of 32 MUFU logs/thread.
    __shared__ float4 s_gt[B_ * G_];           // 32 KB
    __shared__ float  s_sum[B_ * NWARP];
    __shared__ int    s_cnt[B_ * NWARP];
    __shared__ float  s_img[B_];
    __shared__ unsigned s_ticket;

    const int tid  = threadIdx.x;
    const int lane = tid & 31;
    const int warp = tid >> 5;
    const int a    = blockIdx.x * NTHR + tid;   // NBLK*NTHR == A_, no guard

    // Cooperative coalesced stage: 2048 float4 / 256 threads = 8 each.
#pragma unroll
    for (int i = tid; i < B_ * G_; i += NTHR) {
        float4 g = gt[i];
        float gw = g.z - g.x;
        float gh = g.w - g.y;
        s_gt[i] = make_float4(g.x + 0.5f * gw, g.y + 0.5f * gh,
                              __logf(gw), __logf(gh));
    }

    // Anchor loaded ONCE, reused for all 16 batches.
    float4 an = anchors[a];
    float ex_w  = an.z - an.x;
    float ex_h  = an.w - an.y;
    float ex_cx = an.x + 0.5f * ex_w;
    float ex_cy = an.y + 0.5f * ex_h;
    float iw   = 1.0f / ex_w;
    float ih   = 1.0f / ex_h;
    float lexw = __logf(ex_w);
    float lexh = __logf(ex_h);

    // Front-batch all 16 matched-index loads (MLP).
    int m[B_];
#pragma unroll
    for (int b = 0; b < B_; b++)
        m[b] = midx[(size_t)b * A_ + a];

    __syncthreads();   // s_gt ready

#pragma unroll
    for (int b = 0; b < B_; b++) {
        const bool fg = (m[b] >= 0);
        float4 r = bbox[(size_t)b * A_ + a];
        float4 t = s_gt[b * G_ + (fg ? m[b] : 0)];   // smem gather

        float dx = (t.x - ex_cx) * iw;
        float dy = (t.y - ex_cy) * ih;
        float dw = t.z - lexw;     // log(gw) - log(ex_w)
        float dh = t.w - lexh;

        float l1 = fabsf(r.x - dx) + fabsf(r.y - dy)
                 + fabsf(r.z - dw) + fabsf(r.w - dh);
        l1 = fg ? l1 : 0.0f;

        // Warp reduce: sum via shfl chain, count via ballot+popc.
#pragma unroll
        for (int o = 16; o > 0; o >>= 1)
            l1 += __shfl_down_sync(0xffffffffu, l1, o);
        unsigned bal = __ballot_sync(0xffffffffu, fg);

        if (lane == 0) {
            s_sum[b * NWARP + warp] = l1;
            s_cnt[b * NWARP + warp] = __popc(bal);
        }
    }
    __syncthreads();

    // Deterministic block combine: thread t (<16) owns batch t.
    if (tid < B_) {
        float s = 0.0f;
        int   c = 0;
#pragma unroll
        for (int w = 0; w < NWARP; w++) {
            s += s_sum[tid * NWARP + w];
            c += s_cnt[tid * NWARP + w];
        }
        g_part[tid * NBLK + blockIdx.x] = make_float2(s, (float)c);
    }

    // ---- last-block-done final reduction (single-kernel, graph-safe) ----
    __threadfence();
    __syncthreads();
    if (tid == 0)
        s_ticket = atomicAdd(&g_done, 1u);
    __syncthreads();

    if (s_ticket == (unsigned)(NBLK - 1)) {
        // All partials L2-visible. Warp-per-batch, fixed order -> deterministic.
        for (int b = warp; b < B_; b += NWARP) {
            float s = 0.0f;
            float c = 0.0f;
#pragma unroll 8
            for (int i = lane; i < NBLK; i += 32) {
                float2 p = __ldcg(&g_part[b * NBLK + i]);
                s += p.x;
                c += p.y;
            }
#pragma unroll
            for (int o = 16; o > 0; o >>= 1) {
                s += __shfl_down_sync(0xffffffffu, s, o);
                c += __shfl_down_sync(0xffffffffu, c, o);
            }
            if (lane == 0)
                s_img[b] = s / fmaxf(c, 1.0f);
        }
        __syncthreads();
        if (tid == 0) {
            float tot = 0.0f;
#pragma unroll
            for (int b = 0; b < B_; b++) tot += s_img[b];
            *out = tot * (1.0f / (float)B_);
            g_done = 0;           // reset for the next graph replay
        }
    }
}

extern "C" void kernel_launch(void* const* d_in, const int* in_sizes, int n_in,
                              void* d_out, int out_size)
{
    const float4* bbox    = (const float4*)d_in[0];  // bbox_regression [B, A, 4] f32
    const float4* anchors = (const float4*)d_in[1];  // anchors [A, 4] f32
    const float4* gt      = (const float4*)d_in[2];  // gt_boxes [B, G, 4] f32
    const int*    midx    = (const int*)d_in[3];     // matched_idxs [B, A] i32

    retina_loss_fused<<<NBLK, NTHR>>>(bbox, anchors, gt, midx, (float*)d_out);
}

// round 8
// speedup vs baseline: 1.5140x; 1.5140x over previous
#include <cuda_runtime.h>
#include <cuda_bf16.h>

#define B_    16
#define A_    262144
#define G_    128
#define NTHR  256
#define NBLK  (A_ / NTHR)      /* 1024 */
#define NWARP (NTHR / 32)      /* 8 */

// Pre-transformed gt table: {gcx, gcy, log(gw), log(gh)} per (b, g).
__device__ float4   g_gt[B_ * G_];
// Per-(batch, block) partials: {sum, count}. Written fresh every launch.
__device__ float2   g_part[B_ * NBLK];
__device__ unsigned g_done = 0;   // reset by the last block each launch

// Tiny prologue: 2048 boxes -> derived form. Removes all gt math + MUFU logs
// from the hot loop of the main kernel.
__global__ void prep_gt(const float4* __restrict__ gt)
{
    int i = blockIdx.x * blockDim.x + threadIdx.x;   // 0 .. 2047
    float4 g = gt[i];
    float gw = g.z - g.x;
    float gh = g.w - g.y;
    g_gt[i] = make_float4(g.x + 0.5f * gw, g.y + 0.5f * gh,
                          __logf(gw), __logf(gh));
}

__global__ void __launch_bounds__(NTHR, 7)   // force regs <= 36 -> 7 CTA/SM
retina_loss_fused(const float4* __restrict__ bbox,     // [B, A, 4]
                  const float4* __restrict__ anchors,  // [A, 4]
                  const int*    __restrict__ midx,     // [B, A]
                  float*        __restrict__ out)
{
    __shared__ float s_sum[B_ * NWARP];
    __shared__ int   s_cnt[B_ * NWARP];
    __shared__ float s_img[B_];
    __shared__ unsigned s_ticket;

    const int tid  = threadIdx.x;
    const int lane = tid & 31;
    const int warp = tid >> 5;
    const int a    = blockIdx.x * NTHR + tid;   // NBLK*NTHR == A_, no guard

    // Anchor loaded ONCE, reused for all 16 batches.
    float4 an = anchors[a];
    float ex_w  = an.z - an.x;
    float ex_h  = an.w - an.y;
    float ex_cx = an.x + 0.5f * ex_w;
    float ex_cy = an.y + 0.5f * ex_h;
    float iw   = 1.0f / ex_w;
    float ih   = 1.0f / ex_h;
    float lexw = __logf(ex_w);
    float lexh = __logf(ex_h);

    // Front-batch all 16 matched-index loads (MLP).
    int m[B_];
#pragma unroll
    for (int b = 0; b < B_; b++)
        m[b] = midx[(size_t)b * A_ + a];

#pragma unroll
    for (int b = 0; b < B_; b++) {
        const bool fg = (m[b] >= 0);
        float4 r = bbox[(size_t)b * A_ + a];
        float4 t = g_gt[b * G_ + (fg ? m[b] : 0)];  // 32 KB table, L1-resident

        float dx = (t.x - ex_cx) * iw;
        float dy = (t.y - ex_cy) * ih;
        float dw = t.z - lexw;     // log(gw) - log(ex_w)
        float dh = t.w - lexh;

        float l1 = fabsf(r.x - dx) + fabsf(r.y - dy)
                 + fabsf(r.z - dw) + fabsf(r.w - dh);
        l1 = fg ? l1 : 0.0f;

        // Warp reduce: sum via shfl chain, count via ballot+popc.
#pragma unroll
        for (int o = 16; o > 0; o >>= 1)
            l1 += __shfl_down_sync(0xffffffffu, l1, o);
        unsigned bal = __ballot_sync(0xffffffffu, fg);

        if (lane == 0) {
            s_sum[b * NWARP + warp] = l1;
            s_cnt[b * NWARP + warp] = __popc(bal);
        }
    }
    __syncthreads();

    // Deterministic block combine: thread t (<16) owns batch t.
    if (tid < B_) {
        float s = 0.0f;
        int   c = 0;
#pragma unroll
        for (int w = 0; w < NWARP; w++) {
            s += s_sum[tid * NWARP + w];
            c += s_cnt[tid * NWARP + w];
        }
        g_part[tid * NBLK + blockIdx.x] = make_float2(s, (float)c);
    }

    // ---- last-block-done final reduction (single-kernel tail, graph-safe) ----
    __threadfence();
    __syncthreads();
    if (tid == 0)
        s_ticket = atomicAdd(&g_done, 1u);
    __syncthreads();

    if (s_ticket == (unsigned)(NBLK - 1)) {
        // All partials L2-visible. Warp-per-batch, fixed order -> deterministic.
        for (int b = warp; b < B_; b += NWARP) {
            float s = 0.0f;
            float c = 0.0f;
#pragma unroll 8
            for (int i = lane; i < NBLK; i += 32) {
                float2 p = __ldcg(&g_part[b * NBLK + i]);
                s += p.x;
                c += p.y;
            }
#pragma unroll
            for (int o = 16; o > 0; o >>= 1) {
                s += __shfl_down_sync(0xffffffffu, s, o);
                c += __shfl_down_sync(0xffffffffu, c, o);
            }
            if (lane == 0)
                s_img[b] = s / fmaxf(c, 1.0f);
        }
        __syncthreads();
        if (tid == 0) {
            float tot = 0.0f;
#pragma unroll
            for (int b = 0; b < B_; b++) tot += s_img[b];
            *out = tot * (1.0f / (float)B_);
            g_done = 0;           // reset for the next graph replay
        }
    }
}

extern "C" void kernel_launch(void* const* d_in, const int* in_sizes, int n_in,
                              void* d_out, int out_size)
{
    const float4* bbox    = (const float4*)d_in[0];  // bbox_regression [B, A, 4] f32
    const float4* anchors = (const float4*)d_in[1];  // anchors [A, 4] f32
    const float4* gt      = (const float4*)d_in[2];  // gt_boxes [B, G, 4] f32
    const int*    midx    = (const int*)d_in[3];     // matched_idxs [B, A] i32

    prep_gt<<<(B_ * G_) / NTHR, NTHR>>>(gt);
    retina_loss_fused<<<NBLK, NTHR>>>(bbox, anchors, midx, (float*)d_out);
}

// round 9
// speedup vs baseline: 1.7222x; 1.1375x over previous
#include <cuda_runtime.h>
#include <cuda_bf16.h>

#define B_    16
#define A_    262144
#define G_    128
#define NTHR  256
#define NBLK  (A_ / NTHR)      /* 1024 */
#define NWARP (NTHR / 32)      /* 8 */

// Pre-transformed gt table: {gcx, gcy, log(gw), log(gh)} per (b, g).
__device__ float4   g_gt[B_ * G_];
// Per-batch fg counts (int atomics -> deterministic) and derived weights.
__device__ int      g_cnt[B_];
__device__ float    g_w[B_];
// Per-block weighted partial sums.
__device__ float    g_bpart[NBLK];
__device__ unsigned g_done1 = 0;   // prepass ticket (self-resetting)
__device__ unsigned g_done2 = 0;   // main ticket   (self-resetting)

// ---------------------------------------------------------------------------
// K1: count foreground per batch + pre-transform gt. Reads midx once (16.8MB).
// Last block turns counts into weights w_b = 1/max(1,n_b) and resets state.
// ---------------------------------------------------------------------------
__global__ void __launch_bounds__(NTHR)
prep_kernel(const float4* __restrict__ gt, const int* __restrict__ midx)
{
    __shared__ int s_c[B_ * NWARP];
    __shared__ unsigned s_t;

    const int tid  = threadIdx.x;
    const int lane = tid & 31;
    const int warp = tid >> 5;
    const int a    = blockIdx.x * NTHR + tid;

    // gt pre-transform: first 2048 global threads, one box each.
    if (a < B_ * G_) {
        float4 g = gt[a];
        float gw = g.z - g.x;
        float gh = g.w - g.y;
        g_gt[a] = make_float4(g.x + 0.5f * gw, g.y + 0.5f * gh,
                              __logf(gw), __logf(gh));
    }

#pragma unroll
    for (int b = 0; b < B_; b++) {
        int m = __ldcs(&midx[(size_t)b * A_ + a]);
        unsigned bal = __ballot_sync(0xffffffffu, m >= 0);
        if (lane == 0) s_c[b * NWARP + warp] = __popc(bal);
    }
    __syncthreads();

    if (tid < B_) {
        int c = 0;
#pragma unroll
        for (int w = 0; w < NWARP; w++) c += s_c[tid * NWARP + w];
        atomicAdd(&g_cnt[tid], c);    // int add: order-independent result
    }

    __threadfence();
    __syncthreads();
    if (tid == 0) s_t = atomicAdd(&g_done1, 1u);
    __syncthreads();

    if (s_t == (unsigned)(NBLK - 1)) {
        if (tid < B_) {
            int c = g_cnt[tid];
            g_w[tid]   = 1.0f / (float)(c > 1 ? c : 1);
            g_cnt[tid] = 0;           // reset for next graph replay
        }
        if (tid == 0) g_done1 = 0;
    }
}

// ---------------------------------------------------------------------------
// K2: pure weighted stream-accumulate. No per-batch reduction anywhere in the
// hot loop: each thread folds all 16 batches into 4 rotating scalars, then a
// single warp shfl-reduce + one float partial per block.
// ---------------------------------------------------------------------------
__global__ void __launch_bounds__(NTHR, 7)
retina_loss_main(const float4* __restrict__ bbox,     // [B, A, 4]
                 const float4* __restrict__ anchors,  // [A, 4]
                 const int*    __restrict__ midx,     // [B, A]
                 float*        __restrict__ out)
{
    __shared__ float s_sum[NWARP];
    __shared__ unsigned s_t;

    const int tid  = threadIdx.x;
    const int lane = tid & 31;
    const int warp = tid >> 5;
    const int a    = blockIdx.x * NTHR + tid;   // NBLK*NTHR == A_

    // Anchor loaded ONCE, reused for all 16 batches.
    float4 an = __ldcs(&anchors[a]);
    float ex_w  = an.z - an.x;
    float ex_h  = an.w - an.y;
    float ex_cx = an.x + 0.5f * ex_w;
    float ex_cy = an.y + 0.5f * ex_h;
    float iw   = 1.0f / ex_w;
    float ih   = 1.0f / ex_h;
    float lexw = __logf(ex_w);
    float lexh = __logf(ex_h);

    // Front-batch all 16 matched-index loads (MLP).
    int m[B_];
#pragma unroll
    for (int b = 0; b < B_; b++)
        m[b] = __ldcs(&midx[(size_t)b * A_ + a]);

    float s0 = 0.0f, s1 = 0.0f, s2 = 0.0f, s3 = 0.0f;

#pragma unroll
    for (int b = 0; b < B_; b++) {
        const bool fg = (m[b] >= 0);
        float4 r = __ldcs(&bbox[(size_t)b * A_ + a]);
        float4 t = g_gt[b * G_ + (fg ? m[b] : 0)];  // 32 KB table, L1-resident
        float  wb = __ldg(&g_w[b]);                 // uniform, L1-hit

        float dx = (t.x - ex_cx) * iw;
        float dy = (t.y - ex_cy) * ih;
        float dw = t.z - lexw;     // log(gw) - log(ex_w)
        float dh = t.w - lexh;

        float l1 = fabsf(r.x - dx) + fabsf(r.y - dy)
                 + fabsf(r.z - dw) + fabsf(r.w - dh);
        float c  = fg ? wb * l1 : 0.0f;

        // 4 rotating accumulators: dependency chain length B_/4.
        if      ((b & 3) == 0) s0 += c;
        else if ((b & 3) == 1) s1 += c;
        else if ((b & 3) == 2) s2 += c;
        else                   s3 += c;
    }

    float s = (s0 + s1) + (s2 + s3);

    // ONE warp reduce for the whole thread (vs 16 in-loop chains before).
#pragma unroll
    for (int o = 16; o > 0; o >>= 1)
        s += __shfl_down_sync(0xffffffffu, s, o);
    if (lane == 0) s_sum[warp] = s;
    __syncthreads();

    if (tid == 0) {
        float bs = 0.0f;
#pragma unroll
        for (int w = 0; w < NWARP; w++) bs += s_sum[w];
        g_bpart[blockIdx.x] = bs;
    }

    // ---- last-block final fold (deterministic fixed-order sum) ----
    __threadfence();
    __syncthreads();
    if (tid == 0) s_t = atomicAdd(&g_done2, 1u);
    __syncthreads();

    if (s_t == (unsigned)(NBLK - 1)) {
        // 1024 partials: 4 per thread, fixed order -> deterministic.
        float v = 0.0f;
#pragma unroll
        for (int i = 0; i < NBLK / NTHR; i++)
            v += __ldcg(&g_bpart[tid + i * NTHR]);
#pragma unroll
        for (int o = 16; o > 0; o >>= 1)
            v += __shfl_down_sync(0xffffffffu, v, o);
        if (lane == 0) s_sum[warp] = v;
        __syncthreads();
        if (tid == 0) {
            float tot = 0.0f;
#pragma unroll
            for (int w = 0; w < NWARP; w++) tot += s_sum[w];
            *out = tot * (1.0f / (float)B_);
            g_done2 = 0;          // reset for next graph replay
        }
    }
}

extern "C" void kernel_launch(void* const* d_in, const int* in_sizes, int n_in,
                              void* d_out, int out_size)
{
    const float4* bbox    = (const float4*)d_in[0];  // bbox_regression [B, A, 4] f32
    const float4* anchors = (const float4*)d_in[1];  // anchors [A, 4] f32
    const float4* gt      = (const float4*)d_in[2];  // gt_boxes [B, G, 4] f32
    const int*    midx    = (const int*)d_in[3];     // matched_idxs [B, A] i32

    prep_kernel<<<NBLK, NTHR>>>(gt, midx);
    retina_loss_main<<<NBLK, NTHR>>>(bbox, anchors, midx, (float*)d_out);
}